// round 10
// baseline (speedup 1.0000x reference)
#include <cuda_runtime.h>
#include <cuda_bf16.h>
#include <cstdint>

#define DEV_INLINE __device__ __forceinline__

constexpr int Bb = 8;
constexpr int Nn = 4096;

// ---------------- static device scratch (no allocation) ----------------
__device__ float    g_h32[Bb * Nn * 64];          // h fp32 (8 MB)
__device__ unsigned g_hpk_hi[Bb * (Nn/2) * 64];   // h bf16, node-pair packed (4 MB)

// ============================================================================
// Kernel 1: h[b,n,j] = sum_{m,a} x[b,n,m,a]*W[m,p(j),a,w(j)]
// 128 threads: thread = (4-node group, p); x prefetched one iter ahead.
// ============================================================================
__global__ void __launch_bounds__(128)
spconv_h_kernel(const float* __restrict__ x, const float* __restrict__ wgt)
{
    __shared__ float ws[128 * 64];   // ws[ka*64 + j],  j = p*16 + w
    const int t = threadIdx.x;
    const int b = blockIdx.y;
    const int ng = t >> 2;
    const int p  = t & 3;
    const int node0 = blockIdx.x * 128 + ng * 4;

    for (int idx = t; idx < 128 * 64; idx += 128) {
        int ka = idx >> 6, j = idx & 63;
        int m = ka >> 5, a = ka & 31, pp = j >> 4, w = j & 15;
        ws[idx] = wgt[(((m * 4 + pp) * 32 + a) << 4) + w];
    }
    __syncthreads();

    float acc[4][16];
#pragma unroll
    for (int nd = 0; nd < 4; nd++)
#pragma unroll
        for (int i = 0; i < 16; i++) acc[nd][i] = 0.f;

    const float* xr = x + (size_t)(b * Nn + node0) * 128;
    float4 nxt[4];
#pragma unroll
    for (int nd = 0; nd < 4; nd++) nxt[nd] = *(const float4*)(xr + nd * 128);

#pragma unroll 1
    for (int ka4 = 0; ka4 < 32; ka4++) {
        float4 cur[4];
#pragma unroll
        for (int nd = 0; nd < 4; nd++) cur[nd] = nxt[nd];
        if (ka4 < 31) {
#pragma unroll
            for (int nd = 0; nd < 4; nd++)
                nxt[nd] = *(const float4*)(xr + nd * 128 + (ka4 + 1) * 4);
        }
        float xa[4][4];
#pragma unroll
        for (int nd = 0; nd < 4; nd++) {
            xa[nd][0]=cur[nd].x; xa[nd][1]=cur[nd].y;
            xa[nd][2]=cur[nd].z; xa[nd][3]=cur[nd].w;
        }
#pragma unroll
        for (int i = 0; i < 4; i++) {
            const float4* wr = (const float4*)&ws[(ka4 * 4 + i) * 64 + p * 16];
            float4 w0 = wr[0], w1 = wr[1], w2 = wr[2], w3 = wr[3];
#pragma unroll
            for (int nd = 0; nd < 4; nd++) {
                const float xs = xa[nd][i];
                acc[nd][ 0]=fmaf(xs,w0.x,acc[nd][ 0]); acc[nd][ 1]=fmaf(xs,w0.y,acc[nd][ 1]);
                acc[nd][ 2]=fmaf(xs,w0.z,acc[nd][ 2]); acc[nd][ 3]=fmaf(xs,w0.w,acc[nd][ 3]);
                acc[nd][ 4]=fmaf(xs,w1.x,acc[nd][ 4]); acc[nd][ 5]=fmaf(xs,w1.y,acc[nd][ 5]);
                acc[nd][ 6]=fmaf(xs,w1.z,acc[nd][ 6]); acc[nd][ 7]=fmaf(xs,w1.w,acc[nd][ 7]);
                acc[nd][ 8]=fmaf(xs,w2.x,acc[nd][ 8]); acc[nd][ 9]=fmaf(xs,w2.y,acc[nd][ 9]);
                acc[nd][10]=fmaf(xs,w2.z,acc[nd][10]); acc[nd][11]=fmaf(xs,w2.w,acc[nd][11]);
                acc[nd][12]=fmaf(xs,w3.x,acc[nd][12]); acc[nd][13]=fmaf(xs,w3.y,acc[nd][13]);
                acc[nd][14]=fmaf(xs,w3.z,acc[nd][14]); acc[nd][15]=fmaf(xs,w3.w,acc[nd][15]);
            }
        }
    }

#pragma unroll
    for (int nd = 0; nd < 4; nd++) {
        float* hp = g_h32 + (size_t)(b * Nn + node0 + nd) * 64 + p * 16;
#pragma unroll
        for (int w4 = 0; w4 < 4; w4++)
            *(float4*)(hp + w4 * 4) = make_float4(acc[nd][w4*4+0], acc[nd][w4*4+1],
                                                  acc[nd][w4*4+2], acc[nd][w4*4+3]);
    }

#pragma unroll
    for (int pr = 0; pr < 2; pr++) {
        const size_t pb = ((size_t)(b * 2048 + (node0 >> 1) + pr)) * 64 + p * 16;
        unsigned hi[16];
#pragma unroll
        for (int w = 0; w < 16; w++) {
            __nv_bfloat162 t2 = __floats2bfloat162_rn(acc[pr*2+0][w], acc[pr*2+1][w]);
            hi[w] = *reinterpret_cast<unsigned*>(&t2);
        }
#pragma unroll
        for (int w4 = 0; w4 < 4; w4++)
            *(uint4*)(g_hpk_hi + pb + w4 * 4) =
                make_uint4(hi[w4*4], hi[w4*4+1], hi[w4*4+2], hi[w4*4+3]);
    }
}

// ============================================================================
// Kernel 2: per-batch C = adj @ h, fused rowsum/normalize/self-loop/relu/bias.
// BK=64 (256B/row/visit), cp.async 3-stage, one barrier/tile, 512 thr,
// warp grid 4x4 (tile 16x16), A fp32 stride-68, fragment-time bf16 convert.
// ============================================================================
constexpr int AF_STR  = 68;                    // floats per A row (64 + 4 pad)
constexpr int A_STAGE = 64 * AF_STR;           // 4352 u32
constexpr int B_STR   = 72;                    // u32 per B kpair row
constexpr int B_STAGE = 32 * B_STR;            // 2304 u32
constexpr int STAGES  = 3;
constexpr int OFF_A  = 0;
constexpr int OFF_B  = STAGES * A_STAGE;              // 13056
constexpr int OFF_RS = OFF_B + STAGES * B_STAGE;      // 19968 (64 floats)
constexpr int OFF_RI = OFF_RS + 64;                   // 20032 (64 floats)
constexpr int SMEM_U32 = OFF_RI + 64;                 // 20096
constexpr int SMEM_BYTES = SMEM_U32 * 4;              // 80384

DEV_INLINE void mma_bf16(float* c, const unsigned* a, const unsigned* b) {
    asm volatile(
        "mma.sync.aligned.m16n8k16.row.col.f32.bf16.bf16.f32 "
        "{%0,%1,%2,%3}, {%4,%5,%6,%7}, {%8,%9}, {%0,%1,%2,%3};\n"
        : "+f"(c[0]), "+f"(c[1]), "+f"(c[2]), "+f"(c[3])
        : "r"(a[0]), "r"(a[1]), "r"(a[2]), "r"(a[3]), "r"(b[0]), "r"(b[1]));
}

DEV_INLINE void cp16(uint32_t saddr, const void* gptr) {
    asm volatile("cp.async.cg.shared.global [%0], [%1], 16;\n"
                 :: "r"(saddr), "l"(gptr));
}
DEV_INLINE void cp_commit() { asm volatile("cp.async.commit_group;\n"); }
DEV_INLINE void cp_wait1()  { asm volatile("cp.async.wait_group 1;\n"); }
DEV_INLINE void cp_wait0()  { asm volatile("cp.async.wait_group 0;\n"); }

DEV_INLINE unsigned packbf(float2 v) {
    __nv_bfloat162 t2 = __floats2bfloat162_rn(v.x, v.y);
    return *reinterpret_cast<unsigned*>(&t2);
}

__global__ void __launch_bounds__(512, 2)
spconv_gemm_kernel(const float* __restrict__ adj, const float* __restrict__ bias,
                   float* __restrict__ out)
{
    extern __shared__ unsigned sm[];
    const uint32_t smb = (uint32_t)__cvta_generic_to_shared(sm);

    const int t    = threadIdx.x;
    const int lane = t & 31, warp = t >> 5;
    const int g = lane >> 2, tg = lane & 3;
    const int wrow = warp >> 2, wcol = warp & 3;     // 4 x 4 warp grid
    const int bx = blockIdx.x, b = blockIdx.y;

    // A copy: row = t>>3 (8 thr/row), 32B chunk (t&7) — warp covers 4 full rows
    const int arow = t >> 3, achk = t & 7;
    const float* adj_base =
        adj + ((size_t)(b * Nn) + (size_t)bx * 64 + arow) * Nn + achk * 8;
    const uint32_t sa_base = smb + (OFF_A + arow * AF_STR + achk * 8) * 4;
    // B copy: kpair = t>>4 (32), 16B chunk (t&15)
    const int bkp = t >> 4, bc4 = (t & 15) * 4;
    const unsigned* hpH = g_hpk_hi + (size_t)b * 131072 + bkp * 64 + bc4;
    const uint32_t sb_base = smb + (OFF_B + bkp * B_STR + bc4) * 4;

    float acc[2][4];
#pragma unroll
    for (int nf = 0; nf < 2; nf++)
#pragma unroll
        for (int i = 0; i < 4; i++) acc[nf][i] = 0.f;

    float rsum0 = 0.f, rsum1 = 0.f;
    const int r0 = wrow * 16 + g;

    auto issue = [&](int kt, int s) {
        const float* ga = adj_base + (size_t)kt * 64;
        uint32_t sa = sa_base + s * (A_STAGE * 4);
        cp16(sa,      ga);
        cp16(sa + 16, ga + 4);
        cp16(sb_base + s * (B_STAGE * 4), hpH + (size_t)kt * 2048);
        cp_commit();
    };

    auto compute = [&](int s) {
        const float*    Af = (const float*)(sm + OFF_A + s * A_STAGE);
        const unsigned* Bh = sm + OFF_B + s * B_STAGE;
#pragma unroll
        for (int ks = 0; ks < 4; ks++) {
            unsigned bh[2][2];
#pragma unroll
            for (int nf = 0; nf < 2; nf++) {
                int n = wcol * 16 + nf * 8 + g;
                int k0 = (ks * 8 + tg) * B_STR + n;
                bh[nf][0] = Bh[k0];  bh[nf][1] = Bh[k0 + 4 * B_STR];
            }
            const int kb = ks * 16 + 2 * tg;
            float2 p0 = *(const float2*)(Af + (r0    ) * AF_STR + kb);
            float2 p1 = *(const float2*)(Af + (r0 + 8) * AF_STR + kb);
            float2 p2 = *(const float2*)(Af + (r0    ) * AF_STR + kb + 8);
            float2 p3 = *(const float2*)(Af + (r0 + 8) * AF_STR + kb + 8);
            if (wcol == 0) {
                rsum0 += (p0.x + p0.y) + (p2.x + p2.y);
                rsum1 += (p1.x + p1.y) + (p3.x + p3.y);
            }
            unsigned ah[4];
            ah[0] = packbf(p0); ah[1] = packbf(p1);
            ah[2] = packbf(p2); ah[3] = packbf(p3);
#pragma unroll
            for (int nf = 0; nf < 2; nf++)
                mma_bf16(acc[nf], ah, bh[nf]);
        }
    };

    // ---- 3-stage pipeline, one barrier per tile ----
    issue(0, 0);
    issue(1, 1);
    int s = 0, si = 2;
#pragma unroll 1
    for (int kt = 0; kt < 64; kt++) {
        if (kt >= 62) cp_wait0(); else cp_wait1();
        __syncthreads();
        compute(s);
        if (kt + 2 < 64) issue(kt + 2, si);
        else cp_commit();                 // keep group-count semantics in tail
        s  = (s  == STAGES - 1) ? 0 : s + 1;
        si = (si == STAGES - 1) ? 0 : si + 1;
    }

    // ---- rowsum -> rinv ----
    float* rs   = (float*)(sm + OFF_RS);
    float* rinv = (float*)(sm + OFF_RI);
    __syncthreads();
    if (wcol == 0) {
        rsum0 += __shfl_xor_sync(0xffffffffu, rsum0, 1);
        rsum0 += __shfl_xor_sync(0xffffffffu, rsum0, 2);
        rsum1 += __shfl_xor_sync(0xffffffffu, rsum1, 1);
        rsum1 += __shfl_xor_sync(0xffffffffu, rsum1, 2);
        if (tg == 0) { rs[r0] = rsum0; rs[r0 + 8] = rsum1; }
    }
    __syncthreads();
    if (t < 64) rinv[t] = 1.0f / (1.0f + rs[t]);   // +1 = self loop
    __syncthreads();

    // ---- epilogue: out = relu((S + h)*rinv) + bias ----
#pragma unroll
    for (int nf = 0; nf < 2; nf++) {
        int c  = wcol * 16 + nf * 8 + 2 * tg;
        float ri0 = rinv[r0], ri1 = rinv[r0 + 8];
        int gr0 = bx * 64 + r0;
        size_t o0 = ((size_t)(b * Nn + gr0)) * 64 + c;
        size_t o1 = o0 + (size_t)8 * 64;
        float2 h0 = *(const float2*)(g_h32 + o0);
        float2 h1 = *(const float2*)(g_h32 + o1);
        float bz0 = __ldg(bias + c), bz1 = __ldg(bias + c + 1);
        float2 w0, w1;
        w0.x = fmaxf((acc[nf][0] + h0.x) * ri0, 0.f) + bz0;
        w0.y = fmaxf((acc[nf][1] + h0.y) * ri0, 0.f) + bz1;
        w1.x = fmaxf((acc[nf][2] + h1.x) * ri1, 0.f) + bz0;
        w1.y = fmaxf((acc[nf][3] + h1.y) * ri1, 0.f) + bz1;
        *(float2*)(out + o0) = w0;
        *(float2*)(out + o1) = w1;
    }
}

// ============================================================================
extern "C" void kernel_launch(void* const* d_in, const int* in_sizes, int n_in,
                              void* d_out, int out_size)
{
    const float* x    = (const float*)d_in[0];
    const float* adj  = (const float*)d_in[1];
    const float* wgt  = (const float*)d_in[2];
    const float* bias = (const float*)d_in[3];
    float* out = (float*)d_out;

    cudaFuncSetAttribute(spconv_gemm_kernel,
                         cudaFuncAttributeMaxDynamicSharedMemorySize, SMEM_BYTES);

    spconv_h_kernel<<<dim3(32, 8), 128>>>(x, wgt);
    spconv_gemm_kernel<<<dim3(64, 8), 512, SMEM_BYTES>>>(adj, bias, out);
}

// round 11
// speedup vs baseline: 1.5524x; 1.5524x over previous
#include <cuda_runtime.h>
#include <cuda_bf16.h>
#include <cstdint>

#define DEV_INLINE __device__ __forceinline__

constexpr int Bb = 8;
constexpr int Nn = 4096;

// ---------------- static device scratch (no allocation) ----------------
__device__ float    g_h32[Bb * Nn * 64];          // h fp32 (8 MB)
__device__ unsigned g_hpk_hi[Bb * (Nn/2) * 64];   // h bf16, node-pair packed (4 MB)

// ============================================================================
// Kernel 1: h[b,n,j] = sum_{m,a} x[b,n,m,a]*W[m,p(j),a,w(j)]
// 256 threads: thread = (4-node group, p, k-half). K-split x2 doubles warp
// count (latency cover); kc=1 partials reduced through the weights smem.
// ============================================================================
__global__ void __launch_bounds__(256)
spconv_h_kernel(const float* __restrict__ x, const float* __restrict__ wgt)
{
    __shared__ float ws[128 * 64];   // weights, then reused as reduction buffer
    const int t  = threadIdx.x;
    const int b  = blockIdx.y;
    const int kc = t >> 7;          // k-half 0/1
    const int tt = t & 127;
    const int ng = tt >> 2;         // 0..31
    const int p  = tt & 3;
    const int node0 = blockIdx.x * 128 + ng * 4;

    for (int idx = t; idx < 128 * 64; idx += 256) {
        int ka = idx >> 6, j = idx & 63;
        int m = ka >> 5, a = ka & 31, pp = j >> 4, w = j & 15;
        ws[idx] = wgt[(((m * 4 + pp) * 32 + a) << 4) + w];
    }
    __syncthreads();

    float acc[4][16];
#pragma unroll
    for (int nd = 0; nd < 4; nd++)
#pragma unroll
        for (int i = 0; i < 16; i++) acc[nd][i] = 0.f;

    const int ka4_0 = kc * 16;      // 16 ka4-iters per k-half
    const float* xr = x + (size_t)(b * Nn + node0) * 128 + ka4_0 * 4;
    float4 nxt[4];
#pragma unroll
    for (int nd = 0; nd < 4; nd++) nxt[nd] = *(const float4*)(xr + nd * 128);

#pragma unroll 1
    for (int i4 = 0; i4 < 16; i4++) {
        float4 cur[4];
#pragma unroll
        for (int nd = 0; nd < 4; nd++) cur[nd] = nxt[nd];
        if (i4 < 15) {
#pragma unroll
            for (int nd = 0; nd < 4; nd++)
                nxt[nd] = *(const float4*)(xr + nd * 128 + (i4 + 1) * 4);
        }
        float xa[4][4];
#pragma unroll
        for (int nd = 0; nd < 4; nd++) {
            xa[nd][0]=cur[nd].x; xa[nd][1]=cur[nd].y;
            xa[nd][2]=cur[nd].z; xa[nd][3]=cur[nd].w;
        }
#pragma unroll
        for (int i = 0; i < 4; i++) {
            const float4* wr = (const float4*)&ws[((ka4_0 + i4) * 4 + i) * 64 + p * 16];
            float4 w0 = wr[0], w1 = wr[1], w2 = wr[2], w3 = wr[3];
#pragma unroll
            for (int nd = 0; nd < 4; nd++) {
                const float xs = xa[nd][i];
                acc[nd][ 0]=fmaf(xs,w0.x,acc[nd][ 0]); acc[nd][ 1]=fmaf(xs,w0.y,acc[nd][ 1]);
                acc[nd][ 2]=fmaf(xs,w0.z,acc[nd][ 2]); acc[nd][ 3]=fmaf(xs,w0.w,acc[nd][ 3]);
                acc[nd][ 4]=fmaf(xs,w1.x,acc[nd][ 4]); acc[nd][ 5]=fmaf(xs,w1.y,acc[nd][ 5]);
                acc[nd][ 6]=fmaf(xs,w1.z,acc[nd][ 6]); acc[nd][ 7]=fmaf(xs,w1.w,acc[nd][ 7]);
                acc[nd][ 8]=fmaf(xs,w2.x,acc[nd][ 8]); acc[nd][ 9]=fmaf(xs,w2.y,acc[nd][ 9]);
                acc[nd][10]=fmaf(xs,w2.z,acc[nd][10]); acc[nd][11]=fmaf(xs,w2.w,acc[nd][11]);
                acc[nd][12]=fmaf(xs,w3.x,acc[nd][12]); acc[nd][13]=fmaf(xs,w3.y,acc[nd][13]);
                acc[nd][14]=fmaf(xs,w3.z,acc[nd][14]); acc[nd][15]=fmaf(xs,w3.w,acc[nd][15]);
            }
        }
    }

    // ---- K-split reduction: kc=1 dumps partials into ws (exactly 32 KB) ----
    __syncthreads();                 // everyone done reading weights
    if (kc == 1) {
#pragma unroll
        for (int nd = 0; nd < 4; nd++)
#pragma unroll
            for (int w4 = 0; w4 < 4; w4++)
                *(float4*)&ws[tt * 64 + nd * 16 + w4 * 4] =
                    make_float4(acc[nd][w4*4+0], acc[nd][w4*4+1],
                                acc[nd][w4*4+2], acc[nd][w4*4+3]);
    }
    __syncthreads();
    if (kc == 0) {
#pragma unroll
        for (int nd = 0; nd < 4; nd++)
#pragma unroll
            for (int w = 0; w < 16; w++)
                acc[nd][w] += ws[tt * 64 + nd * 16 + w];

        // fp32 h for epilogue
#pragma unroll
        for (int nd = 0; nd < 4; nd++) {
            float* hp = g_h32 + (size_t)(b * Nn + node0 + nd) * 64 + p * 16;
#pragma unroll
            for (int w4 = 0; w4 < 4; w4++)
                *(float4*)(hp + w4 * 4) = make_float4(acc[nd][w4*4+0], acc[nd][w4*4+1],
                                                      acc[nd][w4*4+2], acc[nd][w4*4+3]);
        }
        // node-pair packed bf16
#pragma unroll
        for (int pr = 0; pr < 2; pr++) {
            const size_t pb = ((size_t)(b * 2048 + (node0 >> 1) + pr)) * 64 + p * 16;
            unsigned hi[16];
#pragma unroll
            for (int w = 0; w < 16; w++) {
                __nv_bfloat162 t2 = __floats2bfloat162_rn(acc[pr*2+0][w], acc[pr*2+1][w]);
                hi[w] = *reinterpret_cast<unsigned*>(&t2);
            }
#pragma unroll
            for (int w4 = 0; w4 < 4; w4++)
                *(uint4*)(g_hpk_hi + pb + w4 * 4) =
                    make_uint4(hi[w4*4], hi[w4*4+1], hi[w4*4+2], hi[w4*4+3]);
        }
    }
}

// ============================================================================
// Kernel 2: R7 skeleton (BK=32, 256 thr, warp tile 16x32, cp.async, one
// barrier/tile) with STAGES=3 + 4 CTAs/SM -> single wave.
// ============================================================================
constexpr int A_ROWSTR = 40;                   // floats per A row (32 + 8 pad)
constexpr int A_STAGE  = 64 * A_ROWSTR;        // 2560 u32
constexpr int B_STR    = 72;                   // u32 per B kpair row
constexpr int B_STAGE  = 16 * B_STR;           // 1152 u32
constexpr int STAGES   = 3;
constexpr int OFF_A  = 0;
constexpr int OFF_B  = STAGES * A_STAGE;              // 7680
constexpr int OFF_RS = OFF_B + STAGES * B_STAGE;      // 11136 (64 floats)
constexpr int OFF_RI = OFF_RS + 64;                   // 11200 (64 floats)
constexpr int SMEM_U32 = OFF_RI + 64;                 // 11264
constexpr int SMEM_BYTES = SMEM_U32 * 4;              // 45056

DEV_INLINE void mma_bf16(float* c, const unsigned* a, const unsigned* b) {
    asm volatile(
        "mma.sync.aligned.m16n8k16.row.col.f32.bf16.bf16.f32 "
        "{%0,%1,%2,%3}, {%4,%5,%6,%7}, {%8,%9}, {%0,%1,%2,%3};\n"
        : "+f"(c[0]), "+f"(c[1]), "+f"(c[2]), "+f"(c[3])
        : "r"(a[0]), "r"(a[1]), "r"(a[2]), "r"(a[3]), "r"(b[0]), "r"(b[1]));
}

DEV_INLINE void cp16(uint32_t saddr, const void* gptr) {
    asm volatile("cp.async.cg.shared.global [%0], [%1], 16;\n"
                 :: "r"(saddr), "l"(gptr));
}
DEV_INLINE void cp_commit() { asm volatile("cp.async.commit_group;\n"); }
DEV_INLINE void cp_wait1()  { asm volatile("cp.async.wait_group 1;\n"); }
DEV_INLINE void cp_wait0()  { asm volatile("cp.async.wait_group 0;\n"); }

DEV_INLINE unsigned packbf(float2 v) {
    __nv_bfloat162 t2 = __floats2bfloat162_rn(v.x, v.y);
    return *reinterpret_cast<unsigned*>(&t2);
}

__global__ void __launch_bounds__(256, 4)
spconv_gemm_kernel(const float* __restrict__ adj, const float* __restrict__ bias,
                   float* __restrict__ out)
{
    extern __shared__ unsigned sm[];
    const uint32_t smb = (uint32_t)__cvta_generic_to_shared(sm);

    const int t    = threadIdx.x;
    const int lane = t & 31, warp = t >> 5;
    const int g = lane >> 2, tg = lane & 3;
    const int wrow = warp >> 1, wcol = warp & 1;     // 4 x 2 warp grid
    const int bx = blockIdx.x, b = blockIdx.y;

    // A copy: thread row t>>2 (0..63), 32B chunk t&3 (coalesced)
    const int arow = t >> 2, achk = t & 3;
    const float* adj_base =
        adj + ((size_t)(b * Nn) + (size_t)bx * 64 + arow) * Nn + achk * 8;
    const uint32_t sa_base = smb + (OFF_A + arow * A_ROWSTR + achk * 8) * 4;
    // B copy: kpair = t>>4, 4 u32 columns
    const int bkp = t >> 4, bn4 = (t & 15) * 4;
    const unsigned* hpH = g_hpk_hi + (size_t)b * 131072 + bkp * 64 + bn4;
    const uint32_t sb_base = smb + (OFF_B + bkp * B_STR + bn4) * 4;

    float acc[4][4];
#pragma unroll
    for (int nf = 0; nf < 4; nf++)
#pragma unroll
        for (int i = 0; i < 4; i++) acc[nf][i] = 0.f;

    float rsum0 = 0.f, rsum1 = 0.f;
    const int r0 = wrow * 16 + g;

    auto issue = [&](int kt, int s) {
        const float* ga = adj_base + (size_t)kt * 32;
        uint32_t sa = sa_base + s * (A_STAGE * 4);
        cp16(sa,      ga);
        cp16(sa + 16, ga + 4);
        cp16(sb_base + s * (B_STAGE * 4), hpH + (size_t)kt * 1024);
        cp_commit();
    };

    auto compute = [&](int s) {
        const float*    Af = (const float*)(sm + OFF_A + s * A_STAGE);
        const unsigned* Bh = sm + OFF_B + s * B_STAGE;
#pragma unroll
        for (int ks = 0; ks < 2; ks++) {
            unsigned bh[4][2];
#pragma unroll
            for (int nf = 0; nf < 4; nf++) {
                int n = wcol * 32 + nf * 8 + g;
                int k0 = (ks * 8 + tg) * B_STR + n;
                bh[nf][0] = Bh[k0];  bh[nf][1] = Bh[k0 + 4 * B_STR];
            }
            const int kb = ks * 16 + 2 * tg;
            float2 p0 = *(const float2*)(Af + (r0    ) * A_ROWSTR + kb);
            float2 p1 = *(const float2*)(Af + (r0 + 8) * A_ROWSTR + kb);
            float2 p2 = *(const float2*)(Af + (r0    ) * A_ROWSTR + kb + 8);
            float2 p3 = *(const float2*)(Af + (r0 + 8) * A_ROWSTR + kb + 8);
            if (wcol == 0) {
                rsum0 += (p0.x + p0.y) + (p2.x + p2.y);
                rsum1 += (p1.x + p1.y) + (p3.x + p3.y);
            }
            unsigned ah[4];
            ah[0] = packbf(p0); ah[1] = packbf(p1);
            ah[2] = packbf(p2); ah[3] = packbf(p3);
#pragma unroll
            for (int nf = 0; nf < 4; nf++)
                mma_bf16(acc[nf], ah, bh[nf]);
        }
    };

    // ---- 3-stage pipeline, one barrier per tile ----
    issue(0, 0);
    issue(1, 1);
    int s = 0, si = 2;
#pragma unroll 1
    for (int kt = 0; kt < 128; kt++) {
        if (kt >= 126) cp_wait0(); else cp_wait1();
        __syncthreads();
        compute(s);
        if (kt + 2 < 128) issue(kt + 2, si);
        else cp_commit();                 // keep group-count semantics in tail
        s  = (s  == STAGES - 1) ? 0 : s + 1;
        si = (si == STAGES - 1) ? 0 : si + 1;
    }

    // ---- rowsum -> rinv ----
    float* rs   = (float*)(sm + OFF_RS);
    float* rinv = (float*)(sm + OFF_RI);
    __syncthreads();
    if (wcol == 0) {
        rsum0 += __shfl_xor_sync(0xffffffffu, rsum0, 1);
        rsum0 += __shfl_xor_sync(0xffffffffu, rsum0, 2);
        rsum1 += __shfl_xor_sync(0xffffffffu, rsum1, 1);
        rsum1 += __shfl_xor_sync(0xffffffffu, rsum1, 2);
        if (tg == 0) { rs[r0] = rsum0; rs[r0 + 8] = rsum1; }
    }
    __syncthreads();
    if (t < 64) rinv[t] = 1.0f / (1.0f + rs[t]);   // +1 = self loop
    __syncthreads();

    // ---- epilogue: out = relu((S + h)*rinv) + bias ----
#pragma unroll
    for (int nf = 0; nf < 4; nf++) {
        int c  = wcol * 32 + nf * 8 + 2 * tg;
        float ri0 = rinv[r0], ri1 = rinv[r0 + 8];
        int gr0 = bx * 64 + r0;
        size_t o0 = ((size_t)(b * Nn + gr0)) * 64 + c;
        size_t o1 = o0 + (size_t)8 * 64;
        float2 h0 = *(const float2*)(g_h32 + o0);
        float2 h1 = *(const float2*)(g_h32 + o1);
        float bz0 = __ldg(bias + c), bz1 = __ldg(bias + c + 1);
        float2 w0, w1;
        w0.x = fmaxf((acc[nf][0] + h0.x) * ri0, 0.f) + bz0;
        w0.y = fmaxf((acc[nf][1] + h0.y) * ri0, 0.f) + bz1;
        w1.x = fmaxf((acc[nf][2] + h1.x) * ri1, 0.f) + bz0;
        w1.y = fmaxf((acc[nf][3] + h1.y) * ri1, 0.f) + bz1;
        *(float2*)(out + o0) = w0;
        *(float2*)(out + o1) = w1;
    }
}

// ============================================================================
extern "C" void kernel_launch(void* const* d_in, const int* in_sizes, int n_in,
                              void* d_out, int out_size)
{
    const float* x    = (const float*)d_in[0];
    const float* adj  = (const float*)d_in[1];
    const float* wgt  = (const float*)d_in[2];
    const float* bias = (const float*)d_in[3];
    float* out = (float*)d_out;

    spconv_h_kernel<<<dim3(32, 8), 256>>>(x, wgt);
    spconv_gemm_kernel<<<dim3(64, 8), 256, SMEM_BYTES>>>(adj, bias, out);
}